// round 8
// baseline (speedup 1.0000x reference)
#include <cuda_runtime.h>
#include <cuda_bf16.h>

#define NQ      65536
#define PP      2048
#define NT      32                 // tiles per side (256/8)
#define NTILES  1024
#define CAPQ    256                // queries per tile bucket (mean 64, sd 8)
#define CAPT    192                // kept nodes per tile (mean ~40-70)
#define LOG2E   1.4426950408889634f
#define THRESH  26.0f              // log2 cut: dropped mass <= 2048*2^-26 ~ 3e-5

// Static device state (zero-initialized at module load; no allocation).
__device__ int      g_ncnt[NTILES];
__device__ float    g_list[(size_t)NTILES * CAPT * 8];   // 6 MB records
__device__ int      g_qcnt[NTILES];                      // reset by k_main tail
__device__ unsigned g_qdat[NTILES * CAPQ];               // packed q<<16|y<<8|x

__device__ __forceinline__ float ex2f(float x) {
    float r; asm("ex2.approx.f32 %0,%1;" : "=f"(r) : "f"(x)); return r;
}

// ---------------------------------------------------------------------------
// K1: one CTA per tile, register-resident (no node table in smem).
// Fuses: query scatter (64 queries/CTA), tile max bound, ballot compaction
// (deterministic ascending order), owner-writes of eval records.
// ---------------------------------------------------------------------------
__global__ __launch_bounds__(128)
void k_prep(const int2* __restrict__ X,
            const int2* __restrict__ pat,
            const float* __restrict__ W2,
            const float* __restrict__ sig) {
    __shared__ float wmax[4];
    __shared__ int   wcnt[4];

    const int tid  = threadIdx.x;
    const int lane = tid & 31;
    const int wrp  = tid >> 5;
    const int t    = blockIdx.x;

    // -- Query scatter: this CTA owns queries [64t, 64t+64) --
    if (tid < 64) {
        int i = t * 64 + tid;
        int2 xy = X[i];
        int tt = (xy.x >> 3) * NT + (xy.y >> 3);
        int pos = atomicAdd(&g_qcnt[tt], 1);
        if (pos < CAPQ)
            g_qdat[tt * CAPQ + pos] =
                ((unsigned)i << 16) | ((unsigned)xy.y << 8) | (unsigned)xy.x;
    }

    const float tx0 = (float)((t >> 5) << 3), ty0 = (float)((t & 31) << 3);
    const float tx1 = tx0 + 7.0f, ty1 = ty0 + 7.0f;

    // -- Pass 1: coalesced load of 16 nodes/thread; compute tile max bound
    //    (farthest corner) and per-node keep metric (clamped nearest point).
    float keepm[16];
    float best = -1e30f;
#pragma unroll
    for (int r = 0; r < 16; r++) {
        int p = wrp * 512 + r * 32 + lane;
        int2 pp = pat[p];
        float px = (float)pp.x, py = (float)pp.y;
        float C = __fdividef(-0.5f * LOG2E, sig[p]);          // negative, MUFU
        float dxm = fmaxf(fabsf(px - tx0), fabsf(px - tx1));
        float dym = fmaxf(fabsf(py - ty0), fabsf(py - ty1));
        best = fmaxf(best, C * fmaf(dxm, dxm, dym * dym));
        float dxc = fmaxf(fmaxf(tx0 - px, px - tx1), 0.0f);
        float dyc = fmaxf(fmaxf(ty0 - py, py - ty1), 0.0f);
        keepm[r] = C * fmaf(dxc, dxc, dyc * dyc);
    }
    for (int o = 16; o; o >>= 1)
        best = fmaxf(best, __shfl_xor_sync(0xffffffffu, best, o));
    if (lane == 0) wmax[wrp] = best;
    __syncthreads();
    const float cut = fmaxf(fmaxf(wmax[0], wmax[1]),
                            fmaxf(wmax[2], wmax[3])) - THRESH;

    // -- Pass 2: register-only ballots --
    unsigned masks[16];
    int mycnt = 0;
#pragma unroll
    for (int r = 0; r < 16; r++) {
        unsigned m = __ballot_sync(0xffffffffu, keepm[r] >= cut);
        masks[r] = m;
        mycnt += __popc(m);
    }
    if (lane == 0) wcnt[wrp] = mycnt;
    __syncthreads();
    int base = 0, total = 0;
#pragma unroll
    for (int w = 0; w < 4; w++) {
        if (w < wrp) base += wcnt[w];
        total += wcnt[w];
    }
    const int nk = total < CAPT ? total : CAPT;

    // -- Pass 3: owner-writes records at deterministic ascending rank --
    float4* dst = (float4*)(g_list + (size_t)t * CAPT * 8);
#pragma unroll
    for (int r = 0; r < 16; r++) {
        unsigned m = masks[r];
        if ((m >> lane) & 1u) {
            int rk = base + __popc(m & ((1u << lane) - 1u));
            if (rk < CAPT) {
                int p = wrp * 512 + r * 32 + lane;
                int2 pp = pat[p];                              // L2-hot reload
                float px = (float)pp.x, py = (float)pp.y;
                float C = __fdividef(-0.5f * LOG2E, sig[p]);
                dst[2 * rk + 0] = make_float4(-2.0f * C * px, -2.0f * C * py,
                                              C * fmaf(px, px, py * py), C);
                dst[2 * rk + 1] = make_float4(W2[p], W2[PP + p],
                                              W2[2 * PP + p], 0.0f);
            }
        }
        base += __popc(m);
    }
    if (tid == 0) g_ncnt[t] = nk;
}

// ---------------------------------------------------------------------------
// K2: per-tile evaluation. 256 threads = 64 query-slots x 4 node-chunks,
// quad shuffle reduce (fixed tree) => bitwise-deterministic output.
// ---------------------------------------------------------------------------
__global__ __launch_bounds__(256)
void k_main(float* __restrict__ out) {
    __shared__ float4 sh[2 * CAPT];          // 6 KB records
    const int tid = threadIdx.x;
    const int t = blockIdx.x;
    const int cnt = min(g_qcnt[t], CAPQ);
    if (cnt == 0) {                          // uniform branch
        if (tid == 0) g_qcnt[t] = 0;
        return;
    }
    const int nn = g_ncnt[t];

    const float4* lst = (const float4*)(g_list + (size_t)t * CAPT * 8);
    for (int i = tid; i < 2 * nn; i += 256)
        sh[i] = lst[i];
    __syncthreads();

    const int chunk = tid & 3;               // node chunk within quad
    const int qslot = tid >> 2;              // 64 query slots
    for (int qb = 0; qb < cnt; qb += 64) {
        int qi = qb + qslot;
        float den = 0.f, n0 = 0.f, n1 = 0.f, n2 = 0.f;
        unsigned d = 0;
        if (qi < cnt) {
            d = g_qdat[t * CAPQ + qi];
            float x0 = (float)(d & 255u);
            float x1 = (float)((d >> 8) & 255u);
            float xx = fmaf(x0, x0, x1 * x1);
#pragma unroll 4
            for (int j = chunk; j < nn; j += 4) {
                float4 a = sh[2 * j];
                float4 b = sh[2 * j + 1];
                float arg = fmaf(a.w, xx, a.z);
                arg = fmaf(a.x, x0, arg);
                arg = fmaf(a.y, x1, arg);
                float e = ex2f(arg);
                den += e;
                n0 = fmaf(e, b.x, n0);
                n1 = fmaf(e, b.y, n1);
                n2 = fmaf(e, b.z, n2);
            }
        }
        // Fixed-tree quad reduction (deterministic)
#pragma unroll
        for (int o = 1; o <= 2; o <<= 1) {
            den += __shfl_xor_sync(0xffffffffu, den, o);
            n0  += __shfl_xor_sync(0xffffffffu, n0,  o);
            n1  += __shfl_xor_sync(0xffffffffu, n1,  o);
            n2  += __shfl_xor_sync(0xffffffffu, n2,  o);
        }
        if (chunk == 0 && qi < cnt) {
            float inv = 1.0f / den;
            int q = (int)(d >> 16);
            out[3 * q + 0] = n0 * inv;
            out[3 * q + 1] = n1 * inv;
            out[3 * q + 2] = n2 * inv;
        }
    }
    __syncthreads();
    if (tid == 0) g_qcnt[t] = 0;             // ready for next graph replay
}

// ---------------------------------------------------------------------------
extern "C" void kernel_launch(void* const* d_in, const int* in_sizes, int n_in,
                              void* d_out, int out_size) {
    const int*   X   = (const int*)d_in[0];     // [N,2] int32
    const int*   pat = (const int*)d_in[1];     // [P,2] int32
    const float* W2  = (const float*)d_in[2];   // [C,P] f32
    const float* sig = (const float*)d_in[3];   // [P]   f32
    float* out = (float*)d_out;
    (void)in_sizes; (void)n_in; (void)out_size;

    k_prep<<<NTILES, 128>>>((const int2*)X, (const int2*)pat, W2, sig);
    k_main<<<NTILES, 256>>>(out);
}

// round 9
// speedup vs baseline: 1.8340x; 1.8340x over previous
#include <cuda_runtime.h>
#include <cuda_bf16.h>

#define NQ      65536
#define PP      2048
#define NT      32                 // tiles per side (256/8)
#define NTILES  1024
#define NREG    256                // 16x16 regions of 16px
#define CAPQ    256                // queries per tile bucket (mean 64)
#define CAPT    192                // kept nodes per tile (mean ~40-70)
#define CAPC    384                // region candidates (mean ~100-170)
#define LOG2E   1.4426950408889634f
#define THRESH  26.0f              // log2 cut: dropped mass <= 2048*2^-26 ~ 3e-5

// Static device state (zero-initialized at module load; no allocation).
__device__ int      g_ncnt[NTILES];
__device__ float    g_list[(size_t)NTILES * CAPT * 8];   // 6 MB records
__device__ int      g_qcnt[NTILES];                      // reset by k_main tail
__device__ unsigned g_qdat[NTILES * CAPQ];               // packed q<<16|y<<8|x

__device__ __forceinline__ float ex2f(float x) {
    float r; asm("ex2.approx.f32 %0,%1;" : "=f"(r) : "f"(x)); return r;
}

// ---------------------------------------------------------------------------
// K1: one CTA per 16x16px region (256 CTAs x 256 thr).
//  - scatter 256 queries
//  - level A: filter 2048 nodes -> ~130 region candidates (smem)
//  - level B: per 8px sub-tile (4), 2 warps each: tile bound + keep + records
// All compaction orders are fixed functions of the data => deterministic.
// ---------------------------------------------------------------------------
__global__ __launch_bounds__(256)
void k_prep(const int2* __restrict__ X,
            const int2* __restrict__ pat,
            const float* __restrict__ W2,
            const float* __restrict__ sig) {
    __shared__ float4 cand[CAPC];        // {px, py, C, bitcast(p)}
    __shared__ float  wred[8];
    __shared__ int    wcnt[8];
    __shared__ float  sbB[4][2];
    __shared__ int    scB[4][2];
    __shared__ int    s_nc;

    const int tid  = threadIdx.x;
    const int lane = tid & 31;
    const int wrp  = tid >> 5;
    const int r    = blockIdx.x;
    const int rx   = r >> 4, ry = r & 15;
    const float X0 = (float)(rx << 4), X1 = X0 + 15.0f;
    const float Y0 = (float)(ry << 4), Y1 = Y0 + 15.0f;

    // -- Query scatter: this CTA owns queries [256r, 256r+256) --
    {
        int i = (r << 8) + tid;
        int2 xy = X[i];
        int tt = (xy.x >> 3) * NT + (xy.y >> 3);
        int pos = atomicAdd(&g_qcnt[tt], 1);
        if (pos < CAPQ)
            g_qdat[tt * CAPQ + pos] =
                ((unsigned)i << 16) | ((unsigned)xy.y << 8) | (unsigned)xy.x;
    }

    // -- Level A: 8 nodes/thread, region bound + keep metric --
    float4 v[8];
    float keepm[8];
    float bestA = -1e30f;
#pragma unroll
    for (int k = 0; k < 8; k++) {
        int p = (k << 8) + tid;                        // coalesced
        int2 pp = pat[p];
        float px = (float)pp.x, py = (float)pp.y;
        float C = __fdividef(-0.5f * LOG2E, sig[p]);   // negative (MUFU rcp)
        float dxm = fmaxf(fabsf(px - X0), fabsf(px - X1));
        float dym = fmaxf(fabsf(py - Y0), fabsf(py - Y1));
        bestA = fmaxf(bestA, C * fmaf(dxm, dxm, dym * dym));
        float dxc = fmaxf(fmaxf(X0 - px, px - X1), 0.0f);
        float dyc = fmaxf(fmaxf(Y0 - py, py - Y1), 0.0f);
        keepm[k] = C * fmaf(dxc, dxc, dyc * dyc);
        v[k] = make_float4(px, py, C, __int_as_float(p));
    }
    for (int o = 16; o; o >>= 1)
        bestA = fmaxf(bestA, __shfl_xor_sync(0xffffffffu, bestA, o));
    if (lane == 0) wred[wrp] = bestA;
    __syncthreads();
    float cutA;
    {
        float b = wred[0];
#pragma unroll
        for (int w = 1; w < 8; w++) b = fmaxf(b, wred[w]);
        cutA = b - THRESH;
    }

    // warp-major ballot compaction of candidates (fixed order)
    int mycnt = 0;
    unsigned masks[8];
#pragma unroll
    for (int k = 0; k < 8; k++) {
        masks[k] = __ballot_sync(0xffffffffu, keepm[k] >= cutA);
        mycnt += __popc(masks[k]);
    }
    if (lane == 0) wcnt[wrp] = mycnt;
    __syncthreads();
    int base = 0, total = 0;
#pragma unroll
    for (int w = 0; w < 8; w++) {
        if (w < wrp) base += wcnt[w];
        total += wcnt[w];
    }
    if (tid == 0) s_nc = total < CAPC ? total : CAPC;
#pragma unroll
    for (int k = 0; k < 8; k++) {
        unsigned m = masks[k];
        if ((m >> lane) & 1u) {
            int rk = base + __popc(m & ((1u << lane) - 1u));
            if (rk < CAPC) cand[rk] = v[k];
        }
        base += __popc(m);
    }
    __syncthreads();
    const int nc = s_nc;

    // -- Level B: warp -> (sub-tile st = wrp>>1, half = wrp&1) --
    const int st   = wrp >> 1;
    const int half = wrp & 1;
    const int stx  = 2 * rx + (st >> 1);
    const int sty  = 2 * ry + (st & 1);
    const float bx0 = (float)(stx << 3), bx1 = bx0 + 7.0f;
    const float by0 = (float)(sty << 3), by1 = by0 + 7.0f;

    const int R  = (nc + 31) >> 5;
    const int Rh = (R + 1) >> 1;
    const int r0 = half ? Rh : 0;
    const int r1 = half ? R : Rh;

    // pass 1: tile max bound over candidates
    float bb = -1e30f;
    for (int rr = r0; rr < r1; rr++) {
        int j = (rr << 5) + lane;
        if (j < nc) {
            float4 c = cand[j];
            float dxm = fmaxf(fabsf(c.x - bx0), fabsf(c.x - bx1));
            float dym = fmaxf(fabsf(c.y - by0), fabsf(c.y - by1));
            bb = fmaxf(bb, c.z * fmaf(dxm, dxm, dym * dym));
        }
    }
    for (int o = 16; o; o >>= 1)
        bb = fmaxf(bb, __shfl_xor_sync(0xffffffffu, bb, o));
    if (lane == 0) sbB[st][half] = bb;
    __syncthreads();
    const float cutB = fmaxf(sbB[st][0], sbB[st][1]) - THRESH;

    // pass 2: keep counts
    int kc = 0;
    for (int rr = r0; rr < r1; rr++) {
        int j = (rr << 5) + lane;
        bool keep = false;
        if (j < nc) {
            float4 c = cand[j];
            float dxc = fmaxf(fmaxf(bx0 - c.x, c.x - bx1), 0.0f);
            float dyc = fmaxf(fmaxf(by0 - c.y, c.y - by1), 0.0f);
            keep = (c.z * fmaf(dxc, dxc, dyc * dyc) >= cutB);
        }
        kc += __popc(__ballot_sync(0xffffffffu, keep));
    }
    if (lane == 0) scB[st][half] = kc;
    __syncthreads();

    const int t = stx * NT + sty;
    int wbase = half ? scB[st][0] : 0;
    // pass 3: write records (order: half0 keeps then half1 keeps; fixed)
    float4* dst = (float4*)(g_list + (size_t)t * CAPT * 8);
    for (int rr = r0; rr < r1; rr++) {
        int j = (rr << 5) + lane;
        bool keep = false;
        float4 c = make_float4(0.f, 0.f, 0.f, 0.f);
        if (j < nc) {
            c = cand[j];
            float dxc = fmaxf(fmaxf(bx0 - c.x, c.x - bx1), 0.0f);
            float dyc = fmaxf(fmaxf(by0 - c.y, c.y - by1), 0.0f);
            keep = (c.z * fmaf(dxc, dxc, dyc * dyc) >= cutB);
        }
        unsigned m = __ballot_sync(0xffffffffu, keep);
        if (keep) {
            int rk = wbase + __popc(m & ((1u << lane) - 1u));
            if (rk < CAPT) {
                int p = __float_as_int(c.w);
                float C = c.z;
                dst[2 * rk + 0] = make_float4(-2.0f * C * c.x, -2.0f * C * c.y,
                                              C * fmaf(c.x, c.x, c.y * c.y), C);
                dst[2 * rk + 1] = make_float4(W2[p], W2[PP + p],
                                              W2[2 * PP + p], 0.0f);
            }
        }
        wbase += __popc(m);
    }
    if (lane == 0 && half == 0) {
        int nkT = scB[st][0] + scB[st][1];
        g_ncnt[t] = nkT < CAPT ? nkT : CAPT;
    }
}

// ---------------------------------------------------------------------------
// K2: per-tile evaluation (R7-proven shape). 128 threads = 64 query-slots
// x 2 node-chunks, smem reduce. Fixed order => deterministic.
// ---------------------------------------------------------------------------
__global__ __launch_bounds__(128)
void k_main(float* __restrict__ out) {
    __shared__ float4 sh[2 * CAPT];          // 6 KB records
    __shared__ float4 red[128];
    const int tid = threadIdx.x;
    const int t = blockIdx.x;
    const int nn = g_ncnt[t];
    const int cnt = min(g_qcnt[t], CAPQ);

    const float4* lst = (const float4*)(g_list + (size_t)t * CAPT * 8);
    for (int i = tid; i < 2 * nn; i += 128)
        sh[i] = lst[i];
    __syncthreads();

    const int chunk = tid >> 6;              // 0 or 1
    const int qslot = tid & 63;
    for (int qb = 0; qb < cnt; qb += 64) {
        int qi = qb + qslot;
        float4 acc = make_float4(0.f, 0.f, 0.f, 0.f);
        if (qi < cnt) {
            unsigned d = g_qdat[t * CAPQ + qi];
            float x0 = (float)(d & 255u);
            float x1 = (float)((d >> 8) & 255u);
            float xx = fmaf(x0, x0, x1 * x1);
#pragma unroll 4
            for (int j = chunk; j < nn; j += 2) {
                float4 a = sh[2 * j];
                float4 b = sh[2 * j + 1];
                float arg = fmaf(a.w, xx, a.z);
                arg = fmaf(a.x, x0, arg);
                arg = fmaf(a.y, x1, arg);
                float e = ex2f(arg);
                acc.x += e;
                acc.y = fmaf(e, b.x, acc.y);
                acc.z = fmaf(e, b.y, acc.z);
                acc.w = fmaf(e, b.z, acc.w);
            }
        }
        red[tid] = acc;
        __syncthreads();
        if (tid < 64 && qb + tid < cnt) {
            float4 a0 = red[tid];
            float4 a1 = red[64 + tid];
            float den = a0.x + a1.x;
            float inv = 1.0f / den;
            int q = (int)(g_qdat[t * CAPQ + qb + tid] >> 16);
            out[3 * q + 0] = (a0.y + a1.y) * inv;
            out[3 * q + 1] = (a0.z + a1.z) * inv;
            out[3 * q + 2] = (a0.w + a1.w) * inv;
        }
        __syncthreads();
    }
    if (tid == 0) g_qcnt[t] = 0;             // ready for next graph replay
}

// ---------------------------------------------------------------------------
extern "C" void kernel_launch(void* const* d_in, const int* in_sizes, int n_in,
                              void* d_out, int out_size) {
    const int*   X   = (const int*)d_in[0];     // [N,2] int32
    const int*   pat = (const int*)d_in[1];     // [P,2] int32
    const float* W2  = (const float*)d_in[2];   // [C,P] f32
    const float* sig = (const float*)d_in[3];   // [P]   f32
    float* out = (float*)d_out;
    (void)in_sizes; (void)n_in; (void)out_size;

    k_prep<<<NREG, 256>>>((const int2*)X, (const int2*)pat, W2, sig);
    k_main<<<NTILES, 128>>>(out);
}